// round 3
// baseline (speedup 1.0000x reference)
#include <cuda_runtime.h>
#include <math.h>

#define NB 8
#define NT 4096
#define ND 512
#define NSER (NB * ND)   // 4096 series
#define TOPK 7
#define TCHUNK 64

// Scratch: transposed input (b, d, t) and per-series coefficients
__device__ float  g_xt[(size_t)NSER * NT];        // 64 MB
__device__ float4 g_coef[NSER * TOPK];

// ---------------------------------------------------------------------------
// Kernel 1: transpose (b, t, d) -> (b, d, t)
// ---------------------------------------------------------------------------
__global__ __launch_bounds__(256) void transpose_kernel(const float* __restrict__ in) {
    __shared__ float tile[32][33];
    int b  = blockIdx.z;
    int t0 = blockIdx.x * 32;
    int d0 = blockIdx.y * 32;
    int tx = threadIdx.x, ty = threadIdx.y;

    const float* inp = in + (size_t)b * NT * ND;
#pragma unroll
    for (int i = 0; i < 32; i += 8)
        tile[ty + i][tx] = inp[(size_t)(t0 + ty + i) * ND + (d0 + tx)];
    __syncthreads();
    float* outp = g_xt + (size_t)b * ND * NT;
#pragma unroll
    for (int i = 0; i < 32; i += 8)
        outp[(size_t)(d0 + ty + i) * NT + (t0 + tx)] = tile[tx][ty + i];
}

// ---------------------------------------------------------------------------
// Kernel 2: per-series radix-4 Stockham FFT (N=4096) + top-7 by amplitude
// ---------------------------------------------------------------------------
__device__ __forceinline__ float2 cmul(float2 a, float2 b) {
    return make_float2(a.x * b.x - a.y * b.y, a.x * b.y + a.y * b.x);
}

extern __shared__ float2 sdyn[];

__global__ __launch_bounds__(256) void fft_topk_kernel() {
    float2* bufA = sdyn;           // 4096 complex
    float2* bufB = sdyn + 4096;    // 4096 complex
    float2* tw   = sdyn + 8192;    // 1024 twiddles: exp(-2*pi*i*j/4096)
    __shared__ float sval[256];
    __shared__ int   sidx[256];
    __shared__ int   win[TOPK];

    int tid = threadIdx.x;
    int series = blockIdx.x;
    const float* x = g_xt + (size_t)series * NT;

    // Build twiddle table
    for (int j = tid; j < 1024; j += 256) {
        float s, c;
        sincospif((float)j * (1.0f / 2048.0f), &s, &c);
        tw[j] = make_float2(c, -s);
    }
    // Load real input as complex
    for (int i = tid; i < NT; i += 256)
        bufA[i] = make_float2(x[i], 0.0f);
    __syncthreads();

    // 6 radix-4 Stockham DIF stages (OTFFT formulation), natural-order in/out
    float2* src = bufA;
    float2* dst = bufB;
    int sh = 0;  // log2(s), s = 4^stage
#pragma unroll
    for (int stage = 0; stage < 6; stage++) {
        int s = 1 << sh;
#pragma unroll
        for (int i = tid; i < 1024; i += 256) {
            int q = i & (s - 1);
            int p = i >> sh;                 // i = q + s*p, s*m = 1024 always
            float2 a = src[i];
            float2 b = src[i + 1024];
            float2 c = src[i + 2048];
            float2 d = src[i + 3072];
            float2 apc  = make_float2(a.x + c.x, a.y + c.y);
            float2 amc  = make_float2(a.x - c.x, a.y - c.y);
            float2 bpd  = make_float2(b.x + d.x, b.y + d.y);
            float2 jbmd = make_float2(-(b.y - d.y), b.x - d.x);  // i*(b-d)
            float2 w1 = tw[p << sh];
            float2 w2 = cmul(w1, w1);
            float2 w3 = cmul(w1, w2);
            int ob = q + (p << (sh + 2));    // q + 4*s*p
            dst[ob]         = make_float2(apc.x + bpd.x, apc.y + bpd.y);
            dst[ob + s]     = cmul(w1, make_float2(amc.x - jbmd.x, amc.y - jbmd.y));
            dst[ob + 2 * s] = cmul(w2, make_float2(apc.x - bpd.x, apc.y - bpd.y));
            dst[ob + 3 * s] = cmul(w3, make_float2(amc.x + jbmd.x, amc.y + jbmd.y));
        }
        __syncthreads();
        float2* tmp = src; src = dst; dst = tmp;
        sh += 2;
    }
    // Spectrum now in src (natural order). Amplitudes^2 for k in [0, 2048).
    float* amp = (float*)dst;
    for (int k = tid; k < 2048; k += 256) {
        float2 v = src[k];
        amp[k] = v.x * v.x + v.y * v.y;
    }
    if (tid == 0) amp[0] = -1.0f;   // exclude DC (k=0); Nyquist k=2048 not scanned
    __syncthreads();

    // 7 rounds of block-wide argmax
    for (int it = 0; it < TOPK; it++) {
        float bv = -2.0f; int bi = 0;
        for (int k = tid; k < 2048; k += 256) {
            float v = amp[k];
            if (v > bv) { bv = v; bi = k; }
        }
        sval[tid] = bv; sidx[tid] = bi;
        __syncthreads();
        for (int off = 128; off > 0; off >>= 1) {
            if (tid < off) {
                float ov = sval[tid + off]; int oi = sidx[tid + off];
                if (ov > sval[tid] || (ov == sval[tid] && oi < sidx[tid])) {
                    sval[tid] = ov; sidx[tid] = oi;
                }
            }
            __syncthreads();
        }
        if (tid == 0) { win[it] = sidx[0]; amp[sidx[0]] = -1.0f; }
        __syncthreads();
    }
    if (tid < TOPK) {
        int k = win[tid];
        float2 v = src[k];
        g_coef[series * TOPK + tid] = make_float4((float)k, 2.0f * v.x, 2.0f * v.y, 0.0f);
    }
}

// ---------------------------------------------------------------------------
// Kernel 3: reconstruction via register-resident complex rotors
// out[b,t,d] = sum_j (2Re_j * cos(2 pi k_j t / 4096) - 2Im_j * sin(...))
// ---------------------------------------------------------------------------
__global__ __launch_bounds__(256) void recon_kernel(float* __restrict__ out) {
    int d  = blockIdx.x * 256 + threadIdx.x;   // gridDim.x = 2
    int b  = blockIdx.z;
    int t0 = blockIdx.y * TCHUNK;
    int series = b * ND + d;

    float c2[TOPK], s2[TOPK], cr[TOPK], si[TOPK], cw[TOPK], sw[TOPK];
#pragma unroll
    for (int j = 0; j < TOPK; j++) {
        float4 cf = __ldg(&g_coef[series * TOPK + j]);
        int k = (int)cf.x;
        c2[j] = cf.y; s2[j] = cf.z;
        int m0 = (k * t0) & 4095;              // exact angle reduction mod 2*pi
        float ss, cc;
        sincospif((float)m0 * (1.0f / 2048.0f), &ss, &cc);
        cr[j] = cc; si[j] = ss;
        sincospif((float)k * (1.0f / 2048.0f), &ss, &cc);
        cw[j] = cc; sw[j] = ss;
    }
    float* op = out + ((size_t)b * NT + t0) * ND + d;
#pragma unroll 4
    for (int tt = 0; tt < TCHUNK; tt++) {
        float acc = 0.0f;
#pragma unroll
        for (int j = 0; j < TOPK; j++)
            acc += c2[j] * cr[j] - s2[j] * si[j];
        op[(size_t)tt * ND] = acc;
#pragma unroll
        for (int j = 0; j < TOPK; j++) {
            float nc = cr[j] * cw[j] - si[j] * sw[j];
            si[j]    = cr[j] * sw[j] + si[j] * cw[j];
            cr[j]    = nc;
        }
    }
}

// ---------------------------------------------------------------------------
extern "C" void kernel_launch(void* const* d_in, const int* in_sizes, int n_in,
                              void* d_out, int out_size) {
    const float* x = (const float*)d_in[0];
    float* out = (float*)d_out;

    dim3 tb(32, 8);
    dim3 tg(NT / 32, ND / 32, NB);
    transpose_kernel<<<tg, tb>>>(x);

    size_t shmem = (size_t)(4096 + 4096 + 1024) * sizeof(float2);  // 73728 B
    cudaFuncSetAttribute(fft_topk_kernel,
                         cudaFuncAttributeMaxDynamicSharedMemorySize, (int)shmem);
    fft_topk_kernel<<<NSER, 256, shmem>>>();

    dim3 rg(ND / 256, NT / TCHUNK, NB);
    recon_kernel<<<rg, 256>>>(out);
}

// round 4
// speedup vs baseline: 1.8291x; 1.8291x over previous
#include <cuda_runtime.h>
#include <math.h>

#define NB 8
#define NT 4096
#define ND 512
#define NSER (NB * ND)   // 4096 series
#define TOPK 7
#define TCHUNK 128

// Scratch: transposed input (b, d, t) and per-series coefficients
__device__ float  g_xt[(size_t)NSER * NT];        // 64 MB
__device__ float4 g_coef[NSER * TOPK];

// ---------------------------------------------------------------------------
// Kernel 1: transpose (b, t, d) -> (b, d, t), float4 both directions
// ---------------------------------------------------------------------------
__global__ __launch_bounds__(256) void transpose_kernel(const float* __restrict__ in) {
    __shared__ float tile[32][33];
    int b  = blockIdx.z;
    int t0 = blockIdx.x * 32;
    int d0 = blockIdx.y * 32;
    int tx = threadIdx.x;   // 0..7
    int ty = threadIdx.y;   // 0..31

    const float4 v = *(const float4*)(in + ((size_t)b * NT + t0 + ty) * ND + d0 + tx * 4);
    tile[ty][tx * 4 + 0] = v.x;
    tile[ty][tx * 4 + 1] = v.y;
    tile[ty][tx * 4 + 2] = v.z;
    tile[ty][tx * 4 + 3] = v.w;
    __syncthreads();
    float4 w = make_float4(tile[tx * 4 + 0][ty], tile[tx * 4 + 1][ty],
                           tile[tx * 4 + 2][ty], tile[tx * 4 + 3][ty]);
    *(float4*)(g_xt + ((size_t)b * ND + d0 + ty) * NT + t0 + tx * 4) = w;
}

// ---------------------------------------------------------------------------
// Kernel 2: per-series radix-16 Stockham FFT (N=4096, 3 stages) + top-7
// ---------------------------------------------------------------------------
__device__ __forceinline__ float2 cmul(float2 a, float2 b) {
    return make_float2(a.x * b.x - a.y * b.y, a.x * b.y + a.y * b.x);
}

// forward DFT4 in place: outputs u=0..3 into A,B,C,D
__device__ __forceinline__ void dft4(float2& A, float2& B, float2& C, float2& D) {
    float2 apc  = make_float2(A.x + C.x, A.y + C.y);
    float2 amc  = make_float2(A.x - C.x, A.y - C.y);
    float2 bpd  = make_float2(B.x + D.x, B.y + D.y);
    float2 jbmd = make_float2(-(B.y - D.y), B.x - D.x);   // i*(B-D)
    A = make_float2(apc.x + bpd.x, apc.y + bpd.y);
    B = make_float2(amc.x - jbmd.x, amc.y - jbmd.y);
    C = make_float2(apc.x - bpd.x, apc.y - bpd.y);
    D = make_float2(amc.x + jbmd.x, amc.y + jbmd.y);
}

#define C8f  0.70710678118654752f
#define C16f 0.92387953251128676f
#define S16f 0.38268343236508977f

// In-place 16-point DFT. After this, slot (4*u1 + u2) holds X[u1 + 4*u2].
__device__ __forceinline__ void dft16(float2* a) {
    // level 1: radix-4 over stride-4 groups; slot r2+4*u1 = t[r2][u1]
#pragma unroll
    for (int r2 = 0; r2 < 4; r2++)
        dft4(a[r2], a[r2 + 4], a[r2 + 8], a[r2 + 12]);
    // twiddle W16^{r2*u1} on slot r2+4*u1
    a[5]  = cmul(a[5],  make_float2( C16f, -S16f));   // e=1
    a[6]  = cmul(a[6],  make_float2( C8f,  -C8f ));   // e=2
    a[7]  = cmul(a[7],  make_float2( S16f, -C16f));   // e=3
    a[9]  = cmul(a[9],  make_float2( C8f,  -C8f ));   // e=2
    a[10] = make_float2(a[10].y, -a[10].x);           // e=4: * -i
    a[11] = cmul(a[11], make_float2(-C8f,  -C8f ));   // e=6
    a[13] = cmul(a[13], make_float2( S16f, -C16f));   // e=3
    a[14] = cmul(a[14], make_float2(-C8f,  -C8f ));   // e=6
    a[15] = cmul(a[15], make_float2(-C16f,  S16f));   // e=9
    // level 2: radix-4 over contiguous groups; slot 4*u1+u2 = X[u1+4*u2]
#pragma unroll
    for (int u1 = 0; u1 < 4; u1++)
        dft4(a[4 * u1 + 0], a[4 * u1 + 1], a[4 * u1 + 2], a[4 * u1 + 3]);
}

// One Stockham radix-16 stage; buf indices go through pad map idx+(idx>>4)
template<int S, int SH, bool TW>
__device__ __forceinline__ void fft_stage(float2* buf, int i) {
    float2 a[16];
#pragma unroll
    for (int r = 0; r < 16; r++) {
        int idx = i + 256 * r;
        a[r] = buf[idx + (idx >> 4)];
    }
    __syncthreads();
    dft16(a);
    int q = i & (S - 1);
    int p = i >> SH;
    if (TW) {
        float sw, cw;
        sincospif((float)(S * p) * (1.0f / 2048.0f), &sw, &cw);
        float2 w1 = make_float2(cw, -sw);     // W_4096^{S*p}
        float2 wu = w1;
#pragma unroll
        for (int u = 1; u < 16; u++) {
            int s = ((u & 3) << 2) | (u >> 2);   // slot holding X[u]
            a[s] = cmul(a[s], wu);
            wu = cmul(wu, w1);
        }
    }
    int ob = q + ((p * S) << 4);   // q + 16*S*p
#pragma unroll
    for (int u = 0; u < 16; u++) {
        int s = ((u & 3) << 2) | (u >> 2);
        int idx = ob + S * u;
        buf[idx + (idx >> 4)] = a[s];
    }
    __syncthreads();
}

extern __shared__ float2 sdyn[];

__global__ __launch_bounds__(256) void fft_topk_kernel() {
    float2* buf = sdyn;                    // 4352 float2 (padded 4096)
    float*  amp = (float*)(sdyn + 4352);   // 2048 floats
    __shared__ unsigned long long wmax[8];
    __shared__ int win[TOPK];

    int tid = threadIdx.x;
    const float* x = g_xt + (size_t)blockIdx.x * NT;

#pragma unroll
    for (int r = 0; r < 16; r++) {
        int idx = tid + 256 * r;
        buf[idx + (idx >> 4)] = make_float2(x[idx], 0.0f);
    }
    __syncthreads();

    fft_stage<1,   0, true >(buf, tid);
    fft_stage<16,  4, true >(buf, tid);
    fft_stage<256, 8, false>(buf, tid);

    // amplitudes^2 for k in [0,2048); kill DC
#pragma unroll
    for (int r = 0; r < 8; r++) {
        int k = tid + 256 * r;
        float2 v = buf[k + (k >> 4)];
        amp[k] = (k == 0) ? 0.0f : (v.x * v.x + v.y * v.y);
    }
    __syncthreads();

    int lane = tid & 31, wid = tid >> 5;
    for (int it = 0; it < TOPK; it++) {
        unsigned long long best = 0ull;
#pragma unroll
        for (int r = 0; r < 8; r++) {
            int k = tid + 256 * r;
            unsigned long long pk =
                ((unsigned long long)__float_as_uint(amp[k]) << 32) | (unsigned)(4095 - k);
            if (pk > best) best = pk;
        }
#pragma unroll
        for (int off = 16; off; off >>= 1) {
            unsigned long long o = __shfl_xor_sync(0xffffffffu, best, off);
            if (o > best) best = o;
        }
        if (lane == 0) wmax[wid] = best;
        __syncthreads();
        if (tid == 0) {
            unsigned long long b = wmax[0];
#pragma unroll
            for (int w = 1; w < 8; w++) if (wmax[w] > b) b = wmax[w];
            int k = 4095 - (int)(unsigned)(b & 0xffffffffull);
            win[it] = k;
            amp[k] = 0.0f;   // remove winner
        }
        __syncthreads();
    }
    if (tid < TOPK) {
        int k = win[tid];
        float2 v = buf[k + (k >> 4)];
        g_coef[blockIdx.x * TOPK + tid] = make_float4((float)k, 2.0f * v.x, 2.0f * v.y, 0.0f);
    }
}

// ---------------------------------------------------------------------------
// Kernel 3: reconstruction via register-resident complex rotors
// out[b,t,d] = sum_j (2Re_j * cos(2 pi k_j t / 4096) - 2Im_j * sin(...))
// ---------------------------------------------------------------------------
__global__ __launch_bounds__(256) void recon_kernel(float* __restrict__ out) {
    int d  = blockIdx.x * 256 + threadIdx.x;   // gridDim.x = 2
    int b  = blockIdx.z;
    int t0 = blockIdx.y * TCHUNK;
    int series = b * ND + d;

    float c2[TOPK], s2[TOPK], cr[TOPK], si[TOPK], cw[TOPK], sw[TOPK];
#pragma unroll
    for (int j = 0; j < TOPK; j++) {
        float4 cf = __ldg(&g_coef[series * TOPK + j]);
        int k = (int)cf.x;
        c2[j] = cf.y; s2[j] = cf.z;
        int m0 = (k * t0) & 4095;              // exact angle reduction mod 2*pi
        float ss, cc;
        sincospif((float)m0 * (1.0f / 2048.0f), &ss, &cc);
        cr[j] = cc; si[j] = ss;
        sincospif((float)k * (1.0f / 2048.0f), &ss, &cc);
        cw[j] = cc; sw[j] = ss;
    }
    float* op = out + ((size_t)b * NT + t0) * ND + d;
#pragma unroll 4
    for (int tt = 0; tt < TCHUNK; tt++) {
        float acc = 0.0f;
#pragma unroll
        for (int j = 0; j < TOPK; j++)
            acc += c2[j] * cr[j] - s2[j] * si[j];
        op[(size_t)tt * ND] = acc;
#pragma unroll
        for (int j = 0; j < TOPK; j++) {
            float nc = cr[j] * cw[j] - si[j] * sw[j];
            si[j]    = cr[j] * sw[j] + si[j] * cw[j];
            cr[j]    = nc;
        }
    }
}

// ---------------------------------------------------------------------------
extern "C" void kernel_launch(void* const* d_in, const int* in_sizes, int n_in,
                              void* d_out, int out_size) {
    const float* x = (const float*)d_in[0];
    float* out = (float*)d_out;

    dim3 tb(8, 32);
    dim3 tg(NT / 32, ND / 32, NB);
    transpose_kernel<<<tg, tb>>>(x);

    size_t shmem = 4352 * sizeof(float2) + 2048 * sizeof(float);  // 43008 B
    fft_topk_kernel<<<NSER, 256, shmem>>>();

    dim3 rg(ND / 256, NT / TCHUNK, NB);
    recon_kernel<<<rg, 256>>>(out);
}

// round 5
// speedup vs baseline: 2.5339x; 1.3853x over previous
#include <cuda_runtime.h>
#include <math.h>

#define NB 8
#define NT 4096
#define ND 512
#define NSER (NB * ND)   // 4096 series
#define TOPK 7
#define TCHUNK 128

// Scratch: transposed input (b, d, t) and per-series coefficients
__device__ float  g_xt[(size_t)NSER * NT];        // 64 MB
__device__ float4 g_coef[NSER * TOPK];

// ---------------------------------------------------------------------------
// Kernel 1: transpose (b, t, d) -> (b, d, t); 64t x 32d tile, 2 float4 each way
// ---------------------------------------------------------------------------
__global__ __launch_bounds__(256) void transpose_kernel(const float* __restrict__ in) {
    __shared__ float tile[64][33];
    int b  = blockIdx.z;
    int t0 = blockIdx.x * 64;
    int d0 = blockIdx.y * 32;
    int tx = threadIdx.x;   // 0..7
    int ty = threadIdx.y;   // 0..31

    const float* ip = in + ((size_t)b * NT + t0 + ty) * ND + d0 + tx * 4;
    const float4 v0 = *(const float4*)ip;
    const float4 v1 = *(const float4*)(ip + (size_t)32 * ND);
    tile[ty]     [tx * 4 + 0] = v0.x;
    tile[ty]     [tx * 4 + 1] = v0.y;
    tile[ty]     [tx * 4 + 2] = v0.z;
    tile[ty]     [tx * 4 + 3] = v0.w;
    tile[ty + 32][tx * 4 + 0] = v1.x;
    tile[ty + 32][tx * 4 + 1] = v1.y;
    tile[ty + 32][tx * 4 + 2] = v1.z;
    tile[ty + 32][tx * 4 + 3] = v1.w;
    __syncthreads();
    float4 w0 = make_float4(tile[tx * 4 + 0][ty], tile[tx * 4 + 1][ty],
                            tile[tx * 4 + 2][ty], tile[tx * 4 + 3][ty]);
    float4 w1 = make_float4(tile[tx * 4 + 32][ty], tile[tx * 4 + 33][ty],
                            tile[tx * 4 + 34][ty], tile[tx * 4 + 35][ty]);
    float* op = g_xt + ((size_t)b * ND + d0 + ty) * NT + t0 + tx * 4;
    *(float4*)op        = w0;
    *(float4*)(op + 32) = w1;
}

// ---------------------------------------------------------------------------
// Kernel 2: radix-16 Stockham FFT (N=4096, 3 stages), 2 real series packed
//           per complex FFT, + top-7 per series
// ---------------------------------------------------------------------------
__device__ __forceinline__ float2 cmul(float2 a, float2 b) {
    return make_float2(a.x * b.x - a.y * b.y, a.x * b.y + a.y * b.x);
}

__device__ __forceinline__ void dft4(float2& A, float2& B, float2& C, float2& D) {
    float2 apc  = make_float2(A.x + C.x, A.y + C.y);
    float2 amc  = make_float2(A.x - C.x, A.y - C.y);
    float2 bpd  = make_float2(B.x + D.x, B.y + D.y);
    float2 jbmd = make_float2(-(B.y - D.y), B.x - D.x);   // i*(B-D)
    A = make_float2(apc.x + bpd.x, apc.y + bpd.y);
    B = make_float2(amc.x - jbmd.x, amc.y - jbmd.y);
    C = make_float2(apc.x - bpd.x, apc.y - bpd.y);
    D = make_float2(amc.x + jbmd.x, amc.y + jbmd.y);
}

#define C8f  0.70710678118654752f
#define C16f 0.92387953251128676f
#define S16f 0.38268343236508977f

// In-place 16-point DFT. After this, slot (4*u1 + u2) holds X[u1 + 4*u2].
__device__ __forceinline__ void dft16(float2* a) {
#pragma unroll
    for (int r2 = 0; r2 < 4; r2++)
        dft4(a[r2], a[r2 + 4], a[r2 + 8], a[r2 + 12]);
    a[5]  = cmul(a[5],  make_float2( C16f, -S16f));
    a[6]  = cmul(a[6],  make_float2( C8f,  -C8f ));
    a[7]  = cmul(a[7],  make_float2( S16f, -C16f));
    a[9]  = cmul(a[9],  make_float2( C8f,  -C8f ));
    a[10] = make_float2(a[10].y, -a[10].x);
    a[11] = cmul(a[11], make_float2(-C8f,  -C8f ));
    a[13] = cmul(a[13], make_float2( S16f, -C16f));
    a[14] = cmul(a[14], make_float2(-C8f,  -C8f ));
    a[15] = cmul(a[15], make_float2(-C16f,  S16f));
#pragma unroll
    for (int u1 = 0; u1 < 4; u1++)
        dft4(a[4 * u1 + 0], a[4 * u1 + 1], a[4 * u1 + 2], a[4 * u1 + 3]);
}

template<int S, int SH, bool TW>
__device__ __forceinline__ void fft_stage(float2* buf, int i) {
    float2 a[16];
#pragma unroll
    for (int r = 0; r < 16; r++) {
        int idx = i + 256 * r;
        a[r] = buf[idx + (idx >> 4)];
    }
    __syncthreads();
    dft16(a);
    int q = i & (S - 1);
    int p = i >> SH;
    if (TW) {
        float sw, cw;
        sincospif((float)(S * p) * (1.0f / 2048.0f), &sw, &cw);
        float2 w1 = make_float2(cw, -sw);
        float2 wu = w1;
#pragma unroll
        for (int u = 1; u < 16; u++) {
            int s = ((u & 3) << 2) | (u >> 2);
            a[s] = cmul(a[s], wu);
            wu = cmul(wu, w1);
        }
    }
    int ob = q + ((p * S) << 4);
#pragma unroll
    for (int u = 0; u < 16; u++) {
        int s = ((u & 3) << 2) | (u >> 2);
        int idx = ob + S * u;
        buf[idx + (idx >> 4)] = a[s];
    }
    __syncthreads();
}

extern __shared__ float2 sdyn[];

__global__ __launch_bounds__(256) void fft_topk_kernel() {
    float2* buf  = sdyn;                     // 4352 float2 (padded 4096)
    float*  ampA = (float*)(sdyn + 4352);    // 2048 floats
    float*  ampB = ampA + 2048;              // 2048 floats
    __shared__ unsigned long long wmax[8];
    __shared__ int win[TOPK];

    int tid = threadIdx.x;
    int b = blockIdx.x >> 8;
    int e = blockIdx.x & 255;
    int series0 = b * ND + 2 * e;
    const float* x0 = g_xt + (size_t)series0 * NT;
    const float* x1 = x0 + NT;

    // Pack two real series: Z = x0 + i*x1
#pragma unroll
    for (int r = 0; r < 16; r++) {
        int idx = tid + 256 * r;
        buf[idx + (idx >> 4)] = make_float2(x0[idx], x1[idx]);
    }
    __syncthreads();

    fft_stage<1,   0, true >(buf, tid);
    fft_stage<16,  4, true >(buf, tid);
    fft_stage<256, 8, false>(buf, tid);

    // Unpack: X_a[k] = (Z[k]+conj(Z[N-k]))/2, X_b[k] = -i(Z[k]-conj(Z[N-k]))/2
    // Amps (x4, ranking-invariant) for k in [1, 2048)
#pragma unroll
    for (int r = 0; r < 8; r++) {
        int k = tid + 256 * r;
        if (k == 0) {
            ampA[0] = 0.0f; ampB[0] = 0.0f;
        } else {
            float2 zk = buf[k + (k >> 4)];
            int n = NT - k;
            float2 zn = buf[n + (n >> 4)];
            float ra = zk.x + zn.x, ia = zk.y - zn.y;
            float rb = zk.y + zn.y, ib = zn.x - zk.x;
            ampA[k] = ra * ra + ia * ia;
            ampB[k] = rb * rb + ib * ib;
        }
    }
    __syncthreads();

    int lane = tid & 31, wid = tid >> 5;
    for (int half = 0; half < 2; half++) {
        float* amp = half ? ampB : ampA;
        for (int it = 0; it < TOPK; it++) {
            unsigned long long best = 0ull;
#pragma unroll
            for (int r = 0; r < 8; r++) {
                int k = tid + 256 * r;
                unsigned long long pk =
                    ((unsigned long long)__float_as_uint(amp[k]) << 32) | (unsigned)(4095 - k);
                if (pk > best) best = pk;
            }
#pragma unroll
            for (int off = 16; off; off >>= 1) {
                unsigned long long o = __shfl_xor_sync(0xffffffffu, best, off);
                if (o > best) best = o;
            }
            if (lane == 0) wmax[wid] = best;
            __syncthreads();
            if (tid == 0) {
                unsigned long long bb = wmax[0];
#pragma unroll
                for (int w = 1; w < 8; w++) if (wmax[w] > bb) bb = wmax[w];
                int k = 4095 - (int)(unsigned)(bb & 0xffffffffull);
                win[it] = k;
                amp[k] = 0.0f;
            }
            __syncthreads();
        }
        if (tid < TOPK) {
            int k = win[tid];
            float2 zk = buf[k + (k >> 4)];
            int n = NT - k;
            float2 zn = buf[n + (n >> 4)];
            float re2, im2;   // 2*Re(X), 2*Im(X)
            if (half == 0) { re2 = zk.x + zn.x; im2 = zk.y - zn.y; }
            else           { re2 = zk.y + zn.y; im2 = zn.x - zk.x; }
            g_coef[(series0 + half) * TOPK + tid] =
                make_float4((float)k, re2, im2, 0.0f);
        }
        __syncthreads();
    }
}

// ---------------------------------------------------------------------------
// Kernel 3: reconstruction via Chebyshev recurrence
// y_j[t] = 2Re_j*cos(th) - 2Im_j*sin(th), th = 2*pi*k_j*t/4096
// y_j[t+1] = 2*cos(w_j)*y_j[t] - y_j[t-1]
// ---------------------------------------------------------------------------
__global__ __launch_bounds__(256) void recon_kernel(float* __restrict__ out) {
    int d  = blockIdx.x * 256 + threadIdx.x;   // gridDim.x = 2
    int b  = blockIdx.z;
    int t0 = blockIdx.y * TCHUNK;
    int series = b * ND + d;

    float ycur[TOPK], yprev[TOPK], twocw[TOPK];
#pragma unroll
    for (int j = 0; j < TOPK; j++) {
        float4 cf = __ldg(&g_coef[series * TOPK + j]);
        int k = (int)cf.x;
        float c2 = cf.y, s2 = cf.z;
        int m0 = (k * t0) & 4095;          // exact angle reduction mod 2*pi
        int m1 = (m0 - k) & 4095;          // angle at t0-1
        float ss, cc;
        sincospif((float)m0 * (1.0f / 2048.0f), &ss, &cc);
        ycur[j]  = c2 * cc - s2 * ss;
        sincospif((float)m1 * (1.0f / 2048.0f), &ss, &cc);
        yprev[j] = c2 * cc - s2 * ss;
        sincospif((float)k * (1.0f / 2048.0f), &ss, &cc);
        twocw[j] = 2.0f * cc;
    }
    float* op = out + ((size_t)b * NT + t0) * ND + d;
#pragma unroll 4
    for (int tt = 0; tt < TCHUNK; tt++) {
        float acc = 0.0f;
#pragma unroll
        for (int j = 0; j < TOPK; j++)
            acc += ycur[j];
        op[(size_t)tt * ND] = acc;
#pragma unroll
        for (int j = 0; j < TOPK; j++) {
            float yn = twocw[j] * ycur[j] - yprev[j];
            yprev[j] = ycur[j];
            ycur[j]  = yn;
        }
    }
}

// ---------------------------------------------------------------------------
extern "C" void kernel_launch(void* const* d_in, const int* in_sizes, int n_in,
                              void* d_out, int out_size) {
    const float* x = (const float*)d_in[0];
    float* out = (float*)d_out;

    dim3 tb(8, 32);
    dim3 tg(NT / 64, ND / 32, NB);
    transpose_kernel<<<tg, tb>>>(x);

    size_t shmem = 4352 * sizeof(float2) + 4096 * sizeof(float);  // 51200 B
    cudaFuncSetAttribute(fft_topk_kernel,
                         cudaFuncAttributeMaxDynamicSharedMemorySize, (int)shmem);
    fft_topk_kernel<<<NSER / 2, 256, shmem>>>();

    dim3 rg(ND / 256, NT / TCHUNK, NB);
    recon_kernel<<<rg, 256>>>(out);
}